// round 9
// baseline (speedup 1.0000x reference)
#include <cuda_runtime.h>

#define BB 32
#define SS 2048
#define II 128
#define HH 512
#define OO 64
#define N4 16384            // scan table: tau in [0,4], nearest-neighbor
#define KSC 4096.0f         // N4/4
#define NO 2048             // readout table grid
#define MAGICF 12582912.0f  // 1.5*2^23
#define MAGICI 1262485504   // bits of MAGICF
#define LCH 16
#define NSWEEP 6            // + emission pass = 7 total

#define DOT_BLKS 256
#define TAB_BLKS 65
#define TOUT_BLKS 128       // 16 k-groups x 8 o-groups
#define PREP_BLKS (DOT_BLKS + TAB_BLKS + TOUT_BLKS)

// ---------------- scratch ----------------
__device__ __align__(16) float g_dot[BB*SS];
__device__ __align__(16) float g_G4[N4+260];        // scalar recurrence table
__device__ __align__(16) float g_Gout[NO*OO];       // readout tables

// tau in [0,4) -> diamond direction (S,C), |S|+|C|=1
__device__ __forceinline__ void tau_to_sc(float tau, float& Sv, float& Cv) {
    if (tau >= 4.0f) tau -= 4.0f;
    int q = (int)tau; if (q > 3) q = 3;
    float u = tau - (float)q;
    switch (q) {
        case 0:  Sv = 1.0f - u; Cv = u;        break;
        case 1:  Sv = -u;       Cv = 1.0f - u; break;
        case 2:  Sv = u - 1.0f; Cv = -u;       break;
        default: Sv = u;        Cv = u - 1.0f; break;
    }
}

// one recurrence step; magic-folded rounding, minimal critical chain
__device__ __forceinline__ void scan_step(float c, float& s, const float* __restrict__ tab,
                                          float& m_out, int& ib_out) {
    float ac  = fabsf(c) + 1e-35f;
    float Kac = KSC * ac;
    float Ap, An, BpM;
    if (c >= 0.f) { Ap =  Kac; An = -Kac; BpM = MAGICF; }
    else          { Ap = -Kac; An =  Kac; BpM = MAGICF + 16384.f; }
    float m = fabsf(s) + ac;
    float r; asm("rcp.approx.f32 %0, %1;" : "=f"(r) : "f"(m));
    bool sp = (s >= 0.f);
    float aqs = sp ? Ap  : An;
    float qaK = sp ? BpM : (MAGICF + 8192.f);
    float y  = fmaf(aqs, r, qaK);          // FMA rounds to integer grid (ulp=1)
    int   ib = __float_as_int(y) - MAGICI; // 0..16384
    float g  = tab[ib];
    m_out = m; ib_out = ib;
    s = fmaf(g, 0.1f * m, 0.9f * s);
}

// ---------------- K1: fused prep, roles Bresenham-interleaved -------------
#define PREP_SMEM ((HH*12 + 32*132 + 2*HH) * 4)   // 45.5 KB
__global__ void __launch_bounds__(256)
k_prep(const float* __restrict__ x,  const float* __restrict__ ir,
       const float* __restrict__ ipv, const float* __restrict__ rp,
       const float* __restrict__ rr, const float* __restrict__ W) {
    extern __shared__ float sm[];
    int bx = blockIdx.x, tid = threadIdx.x;

    // interleaved role assignment: A-blocks spread evenly across the grid
    int a0 = (int)(((long long)bx       * DOT_BLKS) / PREP_BLKS);
    int a1 = (int)(((long long)(bx + 1) * DOT_BLKS) / PREP_BLKS);
    bool isA = (a1 > a0);
    int nid = bx - a0;                      // non-A ordinal if !isA

    if (isA) {
        // ---- role A: dot[row] = x[row,:] . ir  (32 rows/warp, 8-row batches) ----
        int w = tid >> 5, lane = tid & 31;
        int rbase = a0 * 256 + w * 32;
        float4 irv = ((const float4*)ir)[lane];
        #pragma unroll
        for (int i = 0; i < 32; i += 8) {
            float4 a[8];
            #pragma unroll
            for (int q = 0; q < 8; ++q)
                a[q] = ((const float4*)(x + (size_t)(rbase + i + q) * II))[lane];
            float p[8];
            #pragma unroll
            for (int q = 0; q < 8; ++q)
                p[q] = a[q].x*irv.x + a[q].y*irv.y + a[q].z*irv.z + a[q].w*irv.w;
            #pragma unroll
            for (int o = 16; o; o >>= 1) {
                #pragma unroll
                for (int q = 0; q < 8; ++q)
                    p[q] += __shfl_xor_sync(0xFFFFFFFFu, p[q], o);
            }
            if (lane == 0) {
                ((float4*)(g_dot + rbase + i))[0] = make_float4(p[0], p[1], p[2], p[3]);
                ((float4*)(g_dot + rbase + i))[1] = make_float4(p[4], p[5], p[6], p[7]);
            }
        }
    } else if (nid < TAB_BLKS) {
        // ---- role B: scan table G4[k] ----
        float* srp = sm; float* sip = sm + HH; float* srr = sm + 2*HH;
        for (int h = tid; h < HH; h += 256) { srp[h]=rp[h]; sip[h]=ipv[h]; srr[h]=rr[h]; }
        __syncthreads();
        int k = nid * 256 + tid;
        if (k < N4 + 8) {
            float Sv, Cv; tau_to_sc((float)k * (4.0f / N4), Sv, Cv);
            float acc = 0.f;
            #pragma unroll 4
            for (int h = 0; h < HH; ++h)
                acc = fmaf(srr[h], fmaxf(fmaf(Sv, srp[h], Cv * sip[h]), 0.f), acc);
            g_G4[k] = acc;
        }
    } else {
        // ---- role C: readout tables, 128k x 8o per block ----
        float* Wsm = sm;                    // [512][12]
        float* su  = sm + HH * 12;          // [32][132]
        float* srp = su + 32 * 132;         // [512]
        float* sip = srp + HH;              // [512]
        int to = nid - TAB_BLKS;
        int kg = to >> 3, og = to & 7;
        int k0 = kg * 128, o0 = og * 8;
        if (tid < 128) {
            ((float4*)srp)[tid] = ((const float4*)rp)[tid];
            ((float4*)sip)[tid] = ((const float4*)ipv)[tid];
        }
        {   // stage W o-tile transposed
            int o = tid >> 5, lane = tid & 31;
            const float4* wr = (const float4*)(W + (size_t)(o0 + o) * HH);
            #pragma unroll
            for (int j = 0; j < 4; ++j) {
                float4 wv = wr[lane + j * 32];
                int h = (lane + j * 32) * 4;
                Wsm[(h+0)*12 + o] = wv.x; Wsm[(h+1)*12 + o] = wv.y;
                Wsm[(h+2)*12 + o] = wv.z; Wsm[(h+3)*12 + o] = wv.w;
            }
        }
        __syncthreads();
        int ku = tid & 127, half = tid >> 7;
        float Svu, Cvu; tau_to_sc((float)(k0 + ku) * (4.0f / NO), Svu, Cvu);
        int km = tid >> 1, oq = tid & 1;
        float4 acc = make_float4(0,0,0,0);
        for (int ht = 0; ht < 16; ++ht) {
            int hb = ht * 32;
            #pragma unroll
            for (int hh = half * 16; hh < half * 16 + 16; ++hh)
                su[hh * 132 + ku] = fmaxf(fmaf(Svu, srp[hb+hh], Cvu * sip[hb+hh]), 0.f);
            __syncthreads();
            #pragma unroll 8
            for (int hh = 0; hh < 32; ++hh) {
                float u  = su[hh * 132 + km];
                float4 w = *(const float4*)&Wsm[(hb + hh) * 12 + 4 * oq];
                acc.x = fmaf(u, w.x, acc.x); acc.y = fmaf(u, w.y, acc.y);
                acc.z = fmaf(u, w.z, acc.z); acc.w = fmaf(u, w.w, acc.w);
            }
            __syncthreads();
        }
        ((float4*)(g_Gout + (size_t)(k0 + km) * OO + o0))[oq] = acc;
    }
}

// ---------------- K2: waveform scan + fused readout (one block per batch) -
// smem: tab[N4+8] | sdot[SS] | smt[SS] (float2) | sbound[136]
#define SCAN_SMEM (((N4 + 8) + SS + 2*SS + 136) * 4)   // 90.7 KB
__global__ void k_scan(float* __restrict__ out, const float* __restrict__ bias) {
    extern __shared__ float sm[];
    float*  tab    = sm;                       // N4+8
    float*  sdot   = sm + (N4 + 8);            // SS
    float2* smt    = (float2*)(sdot + SS);     // SS entries (m, ib-bits)
    float*  sbound = (float*)(smt + SS);       // 136
    int b = blockIdx.x, tid = threadIdx.x;     // 512 threads
    const float4* g4 = (const float4*)g_G4;
    float4* t4 = (float4*)tab;
    for (int i = tid; i < (N4 + 8) / 4; i += 512) t4[i] = g4[i];
    ((float4*)sdot)[tid] = ((const float4*)(g_dot + b * SS))[tid];
    if (tid < 136) sbound[tid] = 0.f;
    __syncthreads();

    float mo; int ibo;
    for (int sw = 0; sw < NSWEEP; ++sw) {
        float s = (tid < 128) ? sbound[tid] : 0.f;
        __syncthreads();
        if (tid < 128) {
            const float* cd = sdot + tid * LCH;
            #pragma unroll
            for (int j = 0; j < LCH; ++j) scan_step(cd[j], s, tab, mo, ibo);
            sbound[tid + 1] = s;
        }
        __syncthreads();
    }
    // emission pass with converged boundaries -> smem
    if (tid < 128) {
        float s = sbound[tid];
        const float* cd = sdot + tid * LCH;
        #pragma unroll
        for (int j = 0; j < LCH; ++j) {
            scan_step(cd[j], s, tab, mo, ibo);
            smt[tid * LCH + j] = make_float2(mo, __int_as_float(ibo));
        }
    }
    __syncthreads();

    // ---- fused readout: 8 t-chunks x 64 o -------------------------------
    int o  = tid & 63, ck = tid >> 6;          // ck 0..7, chunk of 256 steps
    int t0 = ck * 256;
    int tw = (ck == 0) ? 0 : t0 - 128;         // 128-step warmup (0.9^128~1e-6)
    float bv = bias[o];
    float acc = 0.f;
    for (int jb = tw; jb < t0; jb += 16) {
        float gv[16], mm[16];
        #pragma unroll
        for (int q = 0; q < 16; ++q) {
            float2 mt = smt[jb + q];
            int idx = ((__float_as_int(mt.y) + 4) >> 3) & (NO - 1);
            gv[q] = __ldg(&g_Gout[(size_t)idx * OO + o]);
            mm[q] = mt.x;
        }
        #pragma unroll
        for (int q = 0; q < 16; ++q)
            acc = fmaf(0.9f, acc, gv[q] * (0.1f * mm[q]));
    }
    float* op = out + ((size_t)b * SS + t0) * OO + o;
    for (int jb = 0; jb < 256; jb += 16) {
        float gv[16], mm[16];
        #pragma unroll
        for (int q = 0; q < 16; ++q) {
            float2 mt = smt[t0 + jb + q];
            int idx = ((__float_as_int(mt.y) + 4) >> 3) & (NO - 1);
            gv[q] = __ldg(&g_Gout[(size_t)idx * OO + o]);
            mm[q] = mt.x;
        }
        #pragma unroll
        for (int q = 0; q < 16; ++q) {
            acc = fmaf(0.9f, acc, gv[q] * (0.1f * mm[q]));
            op[(jb + q) * OO] = acc + bv;
        }
    }
}

// ---------------- launch ---------------------------------------------------
extern "C" void kernel_launch(void* const* d_in, const int* in_sizes, int n_in,
                              void* d_out, int out_size) {
    const float* x    = (const float*)d_in[0];
    const float* ip   = (const float*)d_in[1];
    const float* ir   = (const float*)d_in[2];
    const float* rp   = (const float*)d_in[3];
    const float* rr   = (const float*)d_in[4];
    const float* W    = (const float*)d_in[5];
    const float* bias = (const float*)d_in[6];
    float* out = (float*)d_out;

    cudaFuncSetAttribute(k_scan, cudaFuncAttributeMaxDynamicSharedMemorySize, SCAN_SMEM);

    k_prep<<<PREP_BLKS, 256, PREP_SMEM>>>(x, ir, ip, rp, rr, W);
    k_scan<<<BB, 512, SCAN_SMEM>>>(out, bias);
}

// round 10
// speedup vs baseline: 1.2768x; 1.2768x over previous
#include <cuda_runtime.h>

#define BB 32
#define SS 2048
#define II 128
#define HH 512
#define OO 64
#define N4 16384            // scan table: tau in [0,4], nearest-neighbor
#define KSC 4096.0f         // N4/4
#define NO 2048             // readout table grid
#define MAGICF 12582912.0f  // 1.5*2^23
#define MAGICI 1262485504   // bits of MAGICF
#define LCH 16
#define NSWEEP 6            // + emission pass = 7 total

#define A_BLKS 512
#define B_BLKS 129
#define PREP_BLKS (A_BLKS + B_BLKS)

#define SCAN_BLKS 32
#define C_BLKS 128          // 16 k-rows x 64 o each
#define K2_BLKS (SCAN_BLKS + C_BLKS)

// ---------------- scratch ----------------
__device__ __align__(16) float  g_dot[BB*SS];
__device__ __align__(16) float2 g_mtau[BB*SS];      // (m, int_bits(ib))
__device__ __align__(16) float  g_G4[N4+260];       // scalar recurrence table
__device__ __align__(16) float  g_Gout[NO*OO];      // readout tables

// tau in [0,4) -> diamond direction (S,C), |S|+|C|=1
__device__ __forceinline__ void tau_to_sc(float tau, float& Sv, float& Cv) {
    if (tau >= 4.0f) tau -= 4.0f;
    int q = (int)tau; if (q > 3) q = 3;
    float u = tau - (float)q;
    switch (q) {
        case 0:  Sv = 1.0f - u; Cv = u;        break;
        case 1:  Sv = -u;       Cv = 1.0f - u; break;
        case 2:  Sv = u - 1.0f; Cv = -u;       break;
        default: Sv = u;        Cv = u - 1.0f; break;
    }
}

// one recurrence step; magic-folded rounding, minimal critical chain
__device__ __forceinline__ void scan_step(float c, float& s, const float* __restrict__ tab,
                                          float& m_out, int& ib_out) {
    float ac  = fabsf(c) + 1e-35f;
    float Kac = KSC * ac;
    float Ap, An, BpM;
    if (c >= 0.f) { Ap =  Kac; An = -Kac; BpM = MAGICF; }
    else          { Ap = -Kac; An =  Kac; BpM = MAGICF + 16384.f; }
    float m = fabsf(s) + ac;
    float r; asm("rcp.approx.f32 %0, %1;" : "=f"(r) : "f"(m));
    bool sp = (s >= 0.f);
    float aqs = sp ? Ap  : An;
    float qaK = sp ? BpM : (MAGICF + 8192.f);
    float y  = fmaf(aqs, r, qaK);          // FMA rounds to integer grid (ulp=1)
    int   ib = __float_as_int(y) - MAGICI; // 0..16384
    float g  = tab[ib];
    m_out = m; ib_out = ib;
    s = fmaf(g, 0.1f * m, 0.9f * s);
}

// ---------------- K1: prep = dot (A) + scan table (B), interleaved --------
__global__ void __launch_bounds__(128)
k_prep(const float* __restrict__ x,  const float* __restrict__ ir,
       const float* __restrict__ ipv, const float* __restrict__ rp,
       const float* __restrict__ rr) {
    __shared__ float sb[3*HH];
    int bx = blockIdx.x, tid = threadIdx.x;
    int a0 = (int)(((long long)bx       * A_BLKS) / PREP_BLKS);
    int a1 = (int)(((long long)(bx + 1) * A_BLKS) / PREP_BLKS);

    if (a1 > a0) {
        // ---- role A: dot rows (32 rows/warp, 8-row batches) ----
        int w = tid >> 5, lane = tid & 31;
        int rbase = a0 * 128 + w * 32;
        float4 irv = ((const float4*)ir)[lane];
        #pragma unroll
        for (int i = 0; i < 32; i += 8) {
            float4 a[8];
            #pragma unroll
            for (int q = 0; q < 8; ++q)
                a[q] = ((const float4*)(x + (size_t)(rbase + i + q) * II))[lane];
            float p[8];
            #pragma unroll
            for (int q = 0; q < 8; ++q)
                p[q] = a[q].x*irv.x + a[q].y*irv.y + a[q].z*irv.z + a[q].w*irv.w;
            #pragma unroll
            for (int o = 16; o; o >>= 1) {
                #pragma unroll
                for (int q = 0; q < 8; ++q)
                    p[q] += __shfl_xor_sync(0xFFFFFFFFu, p[q], o);
            }
            if (lane == 0) {
                ((float4*)(g_dot + rbase + i))[0] = make_float4(p[0], p[1], p[2], p[3]);
                ((float4*)(g_dot + rbase + i))[1] = make_float4(p[4], p[5], p[6], p[7]);
            }
        }
    } else {
        // ---- role B: scan table G4[k] ----
        int nid = bx - a0;
        float* srp = sb; float* sip = sb + HH; float* srr = sb + 2*HH;
        for (int h = tid; h < HH; h += 128) { srp[h]=rp[h]; sip[h]=ipv[h]; srr[h]=rr[h]; }
        __syncthreads();
        int k = nid * 128 + tid;
        if (k < N4 + 8) {
            float Sv, Cv; tau_to_sc((float)k * (4.0f / N4), Sv, Cv);
            float acc = 0.f;
            #pragma unroll 4
            for (int h = 0; h < HH; ++h)
                acc = fmaf(srr[h], fmaxf(fmaf(Sv, srp[h], Cv * sip[h]), 0.f), acc);
            g_G4[k] = acc;
        }
    }
}

// ---------------- K2: scan blocks (0..31) + readout-table GEMM (32..159) --
#define K2_SMEM ((N4 + 8 + SS + 136) * 4)   // 74.3 KB; C role uses 70.7 KB
__global__ void k_scan2(const float* __restrict__ W, const float* __restrict__ rp,
                        const float* __restrict__ ipv) {
    extern __shared__ float sm[];
    int bx = blockIdx.x, tid = threadIdx.x;    // 512 threads

    if (bx < SCAN_BLKS) {
        // ================= scan role =================
        float* tab    = sm;                    // N4+8
        float* sdot   = sm + (N4 + 8);         // SS
        float* sbound = sdot + SS;             // 136
        int b = bx;
        const float4* g4 = (const float4*)g_G4;
        float4* t4 = (float4*)tab;
        for (int i = tid; i < (N4 + 8) / 4; i += 512) t4[i] = g4[i];
        ((float4*)sdot)[tid] = ((const float4*)(g_dot + b * SS))[tid];
        if (tid < 136) sbound[tid] = 0.f;
        __syncthreads();

        float mo; int ibo;
        for (int sw = 0; sw < NSWEEP; ++sw) {
            float s = (tid < 128) ? sbound[tid] : 0.f;
            __syncthreads();
            if (tid < 128) {
                const float* cd = sdot + tid * LCH;
                #pragma unroll
                for (int j = 0; j < LCH; ++j) scan_step(cd[j], s, tab, mo, ibo);
                sbound[tid + 1] = s;
            }
            __syncthreads();
        }
        if (tid < 128) {
            float s = sbound[tid];
            const float* cd = sdot + tid * LCH;
            float2* out = g_mtau + b * SS + tid * LCH;
            #pragma unroll
            for (int j = 0; j < LCH; ++j) {
                scan_step(cd[j], s, tab, mo, ibo);
                out[j] = make_float2(mo, __int_as_float(ibo));
            }
        }
    } else {
        // ================= role C: Gout rows k0..k0+15 =================
        float* su   = sm;                      // [512][16]  32.8 KB
        float* Wsmt = sm + HH * 16;            // [128][66]  33.8 KB
        float* srp  = Wsmt + 128 * 66;         // [512]
        float* sip  = srp + HH;                // [512]
        int c  = bx - SCAN_BLKS;
        int k0 = c * 16;
        if (tid < 128) {
            ((float4*)srp)[tid] = ((const float4*)rp)[tid];
            ((float4*)sip)[tid] = ((const float4*)ipv)[tid];
        }
        __syncthreads();
        {   // su[h][kk] = relu(S*rp + C*ip), kk = 0..15
            int kk = tid & 15, h0 = tid >> 4;  // h0 0..31
            float Sv, Cv; tau_to_sc((float)(k0 + kk) * (4.0f / NO), Sv, Cv);
            #pragma unroll
            for (int j = 0; j < 16; ++j) {
                int h = h0 + 32 * j;
                su[h * 16 + kk] = fmaxf(fmaf(Sv, srp[h], Cv * sip[h]), 0.f);
            }
        }
        int kq = (tid >> 5) & 3, og = tid & 31;
        bool active = (tid < 128);
        float a00=0,a01=0,a10=0,a11=0,a20=0,a21=0,a30=0,a31=0;
        for (int ch = 0; ch < 4; ++ch) {
            int hb = ch * 128;
            __syncthreads();
            {   // stage W[o][hb..hb+127] transposed -> Wsmt[h][o], 512 threads
                int o = tid & 63, hg = tid >> 6;            // hg 0..7, 16 h each
                const float4* wr = (const float4*)(W + (size_t)o * HH + hb + hg * 16);
                #pragma unroll
                for (int j = 0; j < 4; ++j) {
                    float4 wv = wr[j];
                    int h = hg * 16 + j * 4;
                    Wsmt[(h+0)*66 + o] = wv.x; Wsmt[(h+1)*66 + o] = wv.y;
                    Wsmt[(h+2)*66 + o] = wv.z; Wsmt[(h+3)*66 + o] = wv.w;
                }
            }
            __syncthreads();
            if (active) {
                #pragma unroll 4
                for (int h = 0; h < 128; ++h) {
                    float4 u4 = *(const float4*)&su[(hb + h) * 16 + 4 * kq];
                    float2 w2 = *(const float2*)&Wsmt[h * 66 + 2 * og];
                    a00 = fmaf(u4.x, w2.x, a00); a01 = fmaf(u4.x, w2.y, a01);
                    a10 = fmaf(u4.y, w2.x, a10); a11 = fmaf(u4.y, w2.y, a11);
                    a20 = fmaf(u4.z, w2.x, a20); a21 = fmaf(u4.z, w2.y, a21);
                    a30 = fmaf(u4.w, w2.x, a30); a31 = fmaf(u4.w, w2.y, a31);
                }
            }
        }
        if (active) {
            int row = k0 + 4 * kq;
            ((float2*)(g_Gout + (size_t)(row    ) * OO))[og] = make_float2(a00, a01);
            ((float2*)(g_Gout + (size_t)(row + 1) * OO))[og] = make_float2(a10, a11);
            ((float2*)(g_Gout + (size_t)(row + 2) * OO))[og] = make_float2(a20, a21);
            ((float2*)(g_Gout + (size_t)(row + 3) * OO))[og] = make_float2(a30, a31);
        }
    }
}

// ---------------- K3: readout lookup + EMA + bias (512 blocks) ------------
__global__ void k_vo(float* __restrict__ out, const float* __restrict__ bias) {
    __shared__ float2 smt[256];
    int b  = blockIdx.x >> 4;
    int ch = blockIdx.x & 15;
    int t0 = ch * 128;
    int tw = (ch == 0) ? 0 : t0 - 128;
    int nt = t0 + 128 - tw;
    int tid = threadIdx.x;          // 64, one per o
    for (int i = tid; i < nt; i += 64) smt[i] = g_mtau[b * SS + tw + i];
    __syncthreads();
    float bv = bias[tid];
    float acc = 0.f;
    int nwarm = t0 - tw;            // 0 or 128
    for (int jb = 0; jb < nwarm; jb += 16) {
        float gv[16], mm[16];
        #pragma unroll
        for (int q = 0; q < 16; ++q) {
            float2 mt = smt[jb + q];
            int idx = ((__float_as_int(mt.y) + 4) >> 3) & (NO - 1);
            gv[q] = __ldg(&g_Gout[(size_t)idx * OO + tid]);
            mm[q] = mt.x;
        }
        #pragma unroll
        for (int q = 0; q < 16; ++q)
            acc = fmaf(0.9f, acc, gv[q] * (0.1f * mm[q]));
    }
    float* op = out + ((size_t)b * SS + t0) * OO + tid;
    for (int jb = 0; jb < 128; jb += 16) {
        float gv[16], mm[16];
        #pragma unroll
        for (int q = 0; q < 16; ++q) {
            float2 mt = smt[nwarm + jb + q];
            int idx = ((__float_as_int(mt.y) + 4) >> 3) & (NO - 1);
            gv[q] = __ldg(&g_Gout[(size_t)idx * OO + tid]);
            mm[q] = mt.x;
        }
        #pragma unroll
        for (int q = 0; q < 16; ++q) {
            acc = fmaf(0.9f, acc, gv[q] * (0.1f * mm[q]));
            op[(jb + q) * OO] = acc + bv;
        }
    }
}

// ---------------- launch ---------------------------------------------------
extern "C" void kernel_launch(void* const* d_in, const int* in_sizes, int n_in,
                              void* d_out, int out_size) {
    const float* x    = (const float*)d_in[0];
    const float* ip   = (const float*)d_in[1];
    const float* ir   = (const float*)d_in[2];
    const float* rp   = (const float*)d_in[3];
    const float* rr   = (const float*)d_in[4];
    const float* W    = (const float*)d_in[5];
    const float* bias = (const float*)d_in[6];
    float* out = (float*)d_out;

    cudaFuncSetAttribute(k_scan2, cudaFuncAttributeMaxDynamicSharedMemorySize, K2_SMEM);

    k_prep<<<PREP_BLKS, 128>>>(x, ir, ip, rp, rr);
    k_scan2<<<K2_BLKS, 512, K2_SMEM>>>(W, rp, ip);
    k_vo<<<BB*16, 64>>>(out, bias);
}